// round 1
// baseline (speedup 1.0000x reference)
#include <cuda_runtime.h>

// Problem constants
#define NROWS   131072      // 32*4096
#define DDIM    64
#define KCODES  512
#define BM      128         // rows per block
#define XSTRIDE 132         // padded row stride for xs (4d%32 bank spread, 16B aligned)
#define NBLOCKS (NROWS / BM)

#define SMEM_FLOATS (DDIM*KCODES + DDIM*XSTRIDE + KCODES + BM)
#define SMEM_BYTES  (SMEM_FLOATS * 4)

__device__ float g_loss_acc;

__global__ void vq_zero_acc() { g_loss_acc = 0.0f; }

__global__ void vq_finalize(float* out, int loss_pos) {
    // loss = l_commitment + l_codebook = 2 * mean((q-x)^2) over 8388608 elems
    out[loss_pos] = 2.0f * g_loss_acc / 8388608.0f;
}

__device__ __forceinline__ unsigned long long ffma2(unsigned long long a,
                                                    unsigned long long b,
                                                    unsigned long long c) {
    unsigned long long d;
    asm("fma.rn.f32x2 %0, %1, %2, %3;" : "=l"(d) : "l"(a), "l"(b), "l"(c));
    return d;
}

__device__ __forceinline__ unsigned long long dup2(float v) {
    unsigned long long d;
    asm("mov.b64 %0, {%1, %1};" : "=l"(d) : "f"(v));
    return d;
}

__device__ __forceinline__ void unpack2(unsigned long long p, float& lo, float& hi) {
    asm("mov.b64 {%0, %1}, %2;" : "=f"(lo), "=f"(hi) : "l"(p));
}

extern __shared__ float sm[];

__global__ __launch_bounds__(256, 1)
void vq_main_kernel(const float* __restrict__ x,
                    const float* __restrict__ E,
                    float* __restrict__ out) {
    float* es   = sm;                        // [64][512] d-major codebook
    float* xs   = es + DDIM * KCODES;        // [64][XSTRIDE] d-major x tile
    float* hn   = xs + DDIM * XSTRIDE;       // [512] 0.5*||e_k||^2
    int*   idxs = (int*)(hn + KCODES);       // [128] best index per row

    const int tid  = threadIdx.x;
    const int row0 = blockIdx.x * BM;

    // ---- Load codebook E [64][512] (already d-major in gmem), coalesced f4 ----
    {
        const float4* Ev  = (const float4*)E;
        float4*       esv = (float4*)es;
        #pragma unroll
        for (int i = 0; i < 32; ++i)
            esv[tid + i * 256] = Ev[tid + i * 256];
    }

    // ---- Load x tile transposed: gmem [r][d] -> smem xs[d][r] ----
    {
        #pragma unroll
        for (int p = 0; p < 8; ++p) {
            int lin = p * 256 + tid;            // 0..2047
            int r   = lin >> 4;                 // 0..127
            int d4  = (lin & 15) << 2;          // 0,4,..,60
            float4 v = *(const float4*)(x + (size_t)(row0 + r) * DDIM + d4);
            xs[(d4 + 0) * XSTRIDE + r] = v.x;
            xs[(d4 + 1) * XSTRIDE + r] = v.y;
            xs[(d4 + 2) * XSTRIDE + r] = v.z;
            xs[(d4 + 3) * XSTRIDE + r] = v.w;
        }
    }
    __syncthreads();

    // ---- Half-norms of codes ----
    #pragma unroll
    for (int c = 0; c < 2; ++c) {
        int k = tid + c * 256;
        float s = 0.0f;
        #pragma unroll
        for (int d = 0; d < DDIM; ++d) {
            float e = es[d * KCODES + k];
            s = fmaf(e, e, s);
        }
        hn[k] = 0.5f * s;
    }
    __syncthreads();

    // ---- Main score GEMM + running argmax ----
    const int tx = tid & 15;       // code-group
    const int ty = tid >> 4;       // row-group
    float best_s[8];
    int   best_i[8];
    #pragma unroll
    for (int i = 0; i < 8; ++i) { best_s[i] = -3.4e38f; best_i[i] = 0; }

    const float* xrow = xs + ty * 8;

    for (int kt = 0; kt < 4; ++kt) {
        const int k0 = kt * 128 + tx * 8;
        const float* erow = es + k0;

        unsigned long long acc[8][4];
        #pragma unroll
        for (int i = 0; i < 8; ++i)
            #pragma unroll
            for (int j = 0; j < 4; ++j)
                acc[i][j] = 0ull;

        #pragma unroll 8
        for (int d = 0; d < DDIM; ++d) {
            // e: 8 codes = 4 natural f32x2 pairs (contiguous in es)
            ulonglong2 ea = *(const ulonglong2*)(erow + d * KCODES);
            ulonglong2 eb = *(const ulonglong2*)(erow + d * KCODES + 4);
            unsigned long long ep[4] = { ea.x, ea.y, eb.x, eb.y };
            // x: 8 rows, broadcast within warp, duplicate into both halves
            float4 xa = *(const float4*)(xrow + d * XSTRIDE);
            float4 xb = *(const float4*)(xrow + d * XSTRIDE + 4);
            unsigned long long xd[8];
            xd[0] = dup2(xa.x); xd[1] = dup2(xa.y);
            xd[2] = dup2(xa.z); xd[3] = dup2(xa.w);
            xd[4] = dup2(xb.x); xd[5] = dup2(xb.y);
            xd[6] = dup2(xb.z); xd[7] = dup2(xb.w);
            #pragma unroll
            for (int i = 0; i < 8; ++i)
                #pragma unroll
                for (int j = 0; j < 4; ++j)
                    acc[i][j] = ffma2(xd[i], ep[j], acc[i][j]);
        }

        // score = dot - 0.5||e||^2 ; ascending k with strict > keeps first max
        #pragma unroll
        for (int i = 0; i < 8; ++i) {
            #pragma unroll
            for (int j = 0; j < 4; ++j) {
                float s0, s1;
                unpack2(acc[i][j], s0, s1);
                int k = k0 + 2 * j;
                float sc0 = s0 - hn[k];
                float sc1 = s1 - hn[k + 1];
                if (sc0 > best_s[i]) { best_s[i] = sc0; best_i[i] = k; }
                if (sc1 > best_s[i]) { best_s[i] = sc1; best_i[i] = k + 1; }
            }
        }
    }

    // ---- Reduce best across the 16 code-group lanes (xor 1,2,4,8 stays in group) ----
    #pragma unroll
    for (int i = 0; i < 8; ++i) {
        float s  = best_s[i];
        int   bi = best_i[i];
        #pragma unroll
        for (int m = 1; m < 16; m <<= 1) {
            float so = __shfl_xor_sync(0xffffffffu, s, m, 32);
            int   io = __shfl_xor_sync(0xffffffffu, bi, m, 32);
            if (so > s || (so == s && io < bi)) { s = so; bi = io; }
        }
        if (tx == 0) idxs[ty * 8 + i] = bi;
    }
    __syncthreads();

    // ---- Epilogue: gather q, straight-through output, loss partial ----
    const int r = tid >> 1;
    const int h = tid & 1;
    const int kq = idxs[r];
    float lp = 0.0f;
    float* orow = out + (size_t)(row0 + r) * DDIM + h * 32;
    #pragma unroll
    for (int i = 0; i < 32; ++i) {
        int d = h * 32 + i;
        float q    = es[d * KCODES + kq];
        float xv   = xs[d * XSTRIDE + r];
        float diff = q - xv;           // matches sg(q) - inpt
        lp = fmaf(diff, diff, lp);
        orow[i] = xv + diff;           // inpt + sg(q - inpt), same rounding as ref
    }

    // ---- Block loss reduction -> one atomic per block ----
    #pragma unroll
    for (int m = 16; m > 0; m >>= 1)
        lp += __shfl_xor_sync(0xffffffffu, lp, m, 32);
    __shared__ float warpsums[8];
    if ((tid & 31) == 0) warpsums[tid >> 5] = lp;
    __syncthreads();
    if (tid == 0) {
        float s = 0.0f;
        #pragma unroll
        for (int w = 0; w < 8; ++w) s += warpsums[w];
        atomicAdd(&g_loss_acc, s);
    }
}

extern "C" void kernel_launch(void* const* d_in, const int* in_sizes, int n_in,
                              void* d_out, int out_size) {
    const float* x = (const float*)d_in[0];   // inpt [32,4096,64] fp32
    const float* E = (const float*)d_in[1];   // emb_mtrx [64,512] fp32
    float* out = (float*)d_out;               // q (8388608 floats) + loss (1 float)

    cudaFuncSetAttribute(vq_main_kernel,
                         cudaFuncAttributeMaxDynamicSharedMemorySize, SMEM_BYTES);

    vq_zero_acc<<<1, 1>>>();
    vq_main_kernel<<<NBLOCKS, 256, SMEM_BYTES>>>(x, E, out);
    vq_finalize<<<1, 1>>>(out, out_size - 1);
}

// round 5
// speedup vs baseline: 1.5725x; 1.5725x over previous
#include <cuda_runtime.h>
#include <cuda_bf16.h>
#include <cstdint>

#define NROWS 131072
#define DDIM  64
#define KC    512
#define BM    128
#define NBLK  (NROWS / BM)
#define MARGIN_TAU 1e-3f

// padded smem rows: 72 bf16 elements = 144 bytes (conflict-free ldmatrix)
#define RS 144

// smem byte offsets (all 16B aligned)
#define EH_OFF  0                       // 512 x 144
#define EL_OFF  73728
#define XH_OFF  147456                  // 128 x 144
#define XL_OFF  165888
#define HN_OFF  184320                  // 512 floats
#define IDX_OFF 186368                  // 128 ints
#define CNT_OFF 186880                  // 1 int
#define FL_OFF  186884                  // 128 ints
#define SMEM_SZ 187648

__device__ float g_loss_acc;

__global__ void vq_zero_acc() { g_loss_acc = 0.0f; }
__global__ void vq_finalize(float* out, int loss_pos) {
    out[loss_pos] = 2.0f * g_loss_acc / 8388608.0f;
}

__device__ __forceinline__ uint32_t s2u(const void* p) {
    uint32_t a;
    asm("{ .reg .u64 t; cvta.to.shared.u64 t, %1; cvt.u32.u64 %0, t; }" : "=r"(a) : "l"(p));
    return a;
}

#define LDSM4(r, addr) \
    asm volatile("ldmatrix.sync.aligned.m8n8.x4.shared.b16 {%0,%1,%2,%3}, [%4];" \
        : "=r"((r)[0]), "=r"((r)[1]), "=r"((r)[2]), "=r"((r)[3]) : "r"(addr))

#define MMA16816(acc, a, b0, b1) \
    asm volatile("mma.sync.aligned.m16n8k16.row.col.f32.bf16.bf16.f32 " \
        "{%0,%1,%2,%3},{%4,%5,%6,%7},{%8,%9},{%0,%1,%2,%3};" \
        : "+f"((acc)[0]), "+f"((acc)[1]), "+f"((acc)[2]), "+f"((acc)[3]) \
        : "r"((a)[0]), "r"((a)[1]), "r"((a)[2]), "r"((a)[3]), "r"(b0), "r"(b1))

__device__ __forceinline__ uint32_t packbf(float lo, float hi) {
    __nv_bfloat162 v = __floats2bfloat162_rn(lo, hi);
    return *(uint32_t*)&v;
}
__device__ __forceinline__ void split1(float v, float& h, float& l) {
    __nv_bfloat16 hb = __float2bfloat16_rn(v);
    h = __bfloat162float(hb);
    l = v - h;
}

extern __shared__ unsigned char smem[];

__global__ __launch_bounds__(256, 1)
void vq_hmma_kernel(const float* __restrict__ x,
                    const float* __restrict__ E,
                    float* __restrict__ out) {
    const int tid = threadIdx.x;
    const int w   = tid >> 5;
    const int l   = tid & 31;
    const int row0 = blockIdx.x * BM;
    const uint32_t sb = s2u(smem);
    float* hn   = (float*)(smem + HN_OFF);
    int*  idxs  = (int*)(smem + IDX_OFF);
    int*  fcnt  = (int*)(smem + CNT_OFF);
    int*  flagd = (int*)(smem + FL_OFF);

    if (tid == 0) *fcnt = 0;

    // ================= prologue: convert E and x into smem =================
    {
        const int k0 = tid;
        float s0 = 0.f, s1 = 0.f;
        #pragma unroll 8
        for (int d = 0; d < DDIM; d += 2) {
            float a0 = E[d * KC + k0],        a1 = E[(d + 1) * KC + k0];
            float b0 = E[d * KC + k0 + 256],  b1 = E[(d + 1) * KC + k0 + 256];
            s0 = fmaf(a0, a0, fmaf(a1, a1, s0));
            s1 = fmaf(b0, b0, fmaf(b1, b1, s1));
            float ah, al, a1h, a1l, bh, bl, b1h, b1l;
            split1(a0, ah, al);  split1(a1, a1h, a1l);
            split1(b0, bh, bl);  split1(b1, b1h, b1l);
            *(uint32_t*)(smem + EH_OFF + k0 * RS + d * 2)           = packbf(ah, a1h);
            *(uint32_t*)(smem + EL_OFF + k0 * RS + d * 2)           = packbf(al, a1l);
            *(uint32_t*)(smem + EH_OFF + (k0 + 256) * RS + d * 2)   = packbf(bh, b1h);
            *(uint32_t*)(smem + EL_OFF + (k0 + 256) * RS + d * 2)   = packbf(bl, b1l);
        }
        hn[k0]       = 0.5f * s0;
        hn[k0 + 256] = 0.5f * s1;
    }
    {
        const float4* x4 = (const float4*)x + (size_t)row0 * 16;
        #pragma unroll
        for (int i = 0; i < 8; ++i) {
            int idx = tid + i * 256;
            int r = idx >> 4, c4 = idx & 15;
            float4 v = x4[idx];
            float h0,l0,h1,l1,h2,l2,h3,l3;
            split1(v.x, h0, l0); split1(v.y, h1, l1);
            split1(v.z, h2, l2); split1(v.w, h3, l3);
            *(uint2*)(smem + XH_OFF + r * RS + c4 * 8) = make_uint2(packbf(h0, h1), packbf(h2, h3));
            *(uint2*)(smem + XL_OFF + r * RS + c4 * 8) = make_uint2(packbf(l0, l1), packbf(l2, l3));
        }
    }
    __syncthreads();

    // ================= main: each warp does 16 rows x 512 codes =================
    uint32_t Ah[4][4], Al[4][4];
    {
        uint32_t abase = (uint32_t)((w * 16 + (l & 15)) * RS + ((l >> 4) << 4));
        #pragma unroll
        for (int ks = 0; ks < 4; ++ks) {
            LDSM4(Ah[ks], sb + XH_OFF + abase + ks * 32);
            LDSM4(Al[ks], sb + XL_OFF + abase + ks * 32);
        }
    }

    float b1_lo = -3.4e38f, b1_hi = -3.4e38f;
    float b2_lo = -3.4e38f, b2_hi = -3.4e38f;
    int   bi_lo = 0, bi_hi = 0;
    const uint32_t brow = (uint32_t)((l & 7) * RS + ((l >> 3) << 4));

    #pragma unroll 1
    for (int g = 0; g < 16; ++g) {
        float acc[4][4];
        #pragma unroll
        for (int t = 0; t < 4; ++t)
            #pragma unroll
            for (int j = 0; j < 4; ++j) acc[t][j] = 0.f;

        #pragma unroll
        for (int s = 0; s < 2; ++s) {
            uint32_t beh[4][4], bel[4][4];
            #pragma unroll
            for (int t = 0; t < 4; ++t) {
                uint32_t ro = (uint32_t)((g * 32 + t * 8) * RS + s * 64) + brow;
                LDSM4(beh[t], sb + EH_OFF + ro);
                LDSM4(bel[t], sb + EL_OFF + ro);
            }
            #pragma unroll
            for (int kk = 0; kk < 2; ++kk) {
                const int ks = 2 * s + kk;
                #pragma unroll
                for (int t = 0; t < 4; ++t)
                    MMA16816(acc[t], Ah[ks], beh[t][2 * kk], beh[t][2 * kk + 1]);
                #pragma unroll
                for (int t = 0; t < 4; ++t)
                    MMA16816(acc[t], Ah[ks], bel[t][2 * kk], bel[t][2 * kk + 1]);
                #pragma unroll
                for (int t = 0; t < 4; ++t)
                    MMA16816(acc[t], Al[ks], beh[t][2 * kk], beh[t][2 * kk + 1]);
            }
        }
        #pragma unroll
        for (int t = 0; t < 4; ++t) {
            const int col0 = g * 32 + t * 8 + 2 * (l & 3);
            float2 h2 = *(const float2*)(hn + col0);
            float sc;
            sc = acc[t][0] - h2.x;
            if (sc > b1_lo) { b2_lo = b1_lo; b1_lo = sc; bi_lo = col0; }
            else if (sc > b2_lo) b2_lo = sc;
            sc = acc[t][1] - h2.y;
            if (sc > b1_lo) { b2_lo = b1_lo; b1_lo = sc; bi_lo = col0 + 1; }
            else if (sc > b2_lo) b2_lo = sc;
            sc = acc[t][2] - h2.x;
            if (sc > b1_hi) { b2_hi = b1_hi; b1_hi = sc; bi_hi = col0; }
            else if (sc > b2_hi) b2_hi = sc;
            sc = acc[t][3] - h2.y;
            if (sc > b1_hi) { b2_hi = b1_hi; b1_hi = sc; bi_hi = col0 + 1; }
            else if (sc > b2_hi) b2_hi = sc;
        }
    }

    // reduce across the 4 lanes of each row-quad, carrying second-best
    #pragma unroll
    for (int m = 1; m < 4; m <<= 1) {
        float so, s2o; int io;
        so  = __shfl_xor_sync(0xffffffffu, b1_lo, m, 32);
        s2o = __shfl_xor_sync(0xffffffffu, b2_lo, m, 32);
        io  = __shfl_xor_sync(0xffffffffu, bi_lo, m, 32);
        b2_lo = fmaxf(fminf(b1_lo, so), fmaxf(b2_lo, s2o));
        if (so > b1_lo || (so == b1_lo && io < bi_lo)) { b1_lo = so; bi_lo = io; }
        so  = __shfl_xor_sync(0xffffffffu, b1_hi, m, 32);
        s2o = __shfl_xor_sync(0xffffffffu, b2_hi, m, 32);
        io  = __shfl_xor_sync(0xffffffffu, bi_hi, m, 32);
        b2_hi = fmaxf(fminf(b1_hi, so), fmaxf(b2_hi, s2o));
        if (so > b1_hi || (so == b1_hi && io < bi_hi)) { b1_hi = so; bi_hi = io; }
    }
    if ((l & 3) == 0) {
        const int r_lo = w * 16 + (l >> 2);
        const int r_hi = r_lo + 8;
        idxs[r_lo] = bi_lo;
        idxs[r_hi] = bi_hi;
        if (b1_lo - b2_lo < MARGIN_TAU) flagd[atomicAdd(fcnt, 1)] = r_lo;
        if (b1_hi - b2_hi < MARGIN_TAU) flagd[atomicAdd(fcnt, 1)] = r_hi;
    }
    __syncthreads();

    // ===== rescue: bit-exact replica of the R1 scalar scoring for flagged rows =====
    {
        const int cnt = *fcnt;
        for (int j = w; j < cnt; j += 8) {
            const int r = flagd[j];
            const float* xr = x + (size_t)(row0 + r) * DDIM;
            float s[16], t[16];
            #pragma unroll
            for (int i = 0; i < 16; ++i) { s[i] = 0.f; t[i] = 0.f; }
            #pragma unroll 4
            for (int d = 0; d < DDIM; ++d) {
                const float xd = xr[d];
                const float* Ed = E + d * KC + l;
                #pragma unroll
                for (int i = 0; i < 16; ++i) {
                    float e = Ed[i * 32];
                    s[i] = fmaf(xd, e, s[i]);
                    t[i] = fmaf(e, e, t[i]);
                }
            }
            float best = -3.4e38f; int bi = 0;
            #pragma unroll
            for (int i = 0; i < 16; ++i) {
                float sc = s[i] - 0.5f * t[i];
                int k = i * 32 + l;
                if (sc > best) { best = sc; bi = k; }
            }
            #pragma unroll
            for (int m = 1; m < 32; m <<= 1) {
                float so = __shfl_xor_sync(0xffffffffu, best, m, 32);
                int   io = __shfl_xor_sync(0xffffffffu, bi,   m, 32);
                if (so > best || (so == best && io < bi)) { best = so; bi = io; }
            }
            if (l == 0) idxs[r] = bi;
        }
    }
    __syncthreads();

    // ================= epilogue: gather q, straight-through out, loss =================
    float lp = 0.0f;
    if (tid < BM) {
        const int r = tid;
        const int k = idxs[r];
        const size_t grow = (size_t)(row0 + r);
        const float4* xg = (const float4*)(x + grow * DDIM);
        float4* og = (float4*)(out + grow * DDIM);
        #pragma unroll
        for (int j = 0; j < 16; ++j) {
            float q0 = E[(j * 4 + 0) * KC + k];
            float q1 = E[(j * 4 + 1) * KC + k];
            float q2 = E[(j * 4 + 2) * KC + k];
            float q3 = E[(j * 4 + 3) * KC + k];
            float4 xv = xg[j];
            float d0 = q0 - xv.x, d1 = q1 - xv.y, d2 = q2 - xv.z, d3 = q3 - xv.w;
            lp = fmaf(d0, d0, lp); lp = fmaf(d1, d1, lp);
            lp = fmaf(d2, d2, lp); lp = fmaf(d3, d3, lp);
            og[j] = make_float4(xv.x + d0, xv.y + d1, xv.z + d2, xv.w + d3);
        }
    }
    #pragma unroll
    for (int m = 16; m > 0; m >>= 1)
        lp += __shfl_xor_sync(0xffffffffu, lp, m, 32);
    if (w < 4 && l == 0) atomicAdd(&g_loss_acc, lp);
}

extern "C" void kernel_launch(void* const* d_in, const int* in_sizes, int n_in,
                              void* d_out, int out_size) {
    const float* x = (const float*)d_in[0];   // [32,4096,64] fp32
    const float* E = (const float*)d_in[1];   // [64,512] fp32
    float* out = (float*)d_out;

    cudaFuncSetAttribute(vq_hmma_kernel,
                         cudaFuncAttributeMaxDynamicSharedMemorySize, SMEM_SZ);

    vq_zero_acc<<<1, 1>>>();
    vq_hmma_kernel<<<NBLK, 256, SMEM_SZ>>>(x, E, out);
    vq_finalize<<<1, 1>>>(out, out_size - 1);
}

// round 6
// speedup vs baseline: 1.7131x; 1.0894x over previous
#include <cuda_runtime.h>
#include <cuda_bf16.h>
#include <cstdint>

#define NROWS 131072
#define DDIM  64
#define KC    512
#define BM    128
#define NBLK  (NROWS / BM)
#define MARGIN_TAU 1e-3f

// padded smem rows: 72 bf16 elements = 144 bytes (conflict-free ldmatrix)
#define RS 144

// smem byte offsets (all 16B aligned)
#define EH_OFF  0                       // 512 x 144
#define EL_OFF  73728
#define XH_OFF  147456                  // 128 x 144
#define XL_OFF  165888
#define HN_OFF  184320                  // 512 floats
#define IDX_OFF 186368                  // 128 ints
#define CNT_OFF 186880                  // 1 int
#define FL_OFF  186884                  // 128 ints
#define SMEM_SZ 187648

__device__ __align__(16) unsigned char g_Ebuf[147456];   // eh table + el table
__device__ __align__(16) float g_hn[KC];
__device__ float g_loss_acc;
__device__ unsigned int g_done;

__device__ __forceinline__ uint32_t s2u(const void* p) {
    uint32_t a;
    asm("{ .reg .u64 t; cvta.to.shared.u64 t, %1; cvt.u32.u64 %0, t; }" : "=r"(a) : "l"(p));
    return a;
}
__device__ __forceinline__ void cpa16(uint32_t dst, const void* src) {
    asm volatile("cp.async.cg.shared.global [%0], [%1], 16;" :: "r"(dst), "l"(src) : "memory");
}
#define CP_COMMIT() asm volatile("cp.async.commit_group;" ::: "memory")
#define CP_WAIT0()  asm volatile("cp.async.wait_group 0;" ::: "memory")

#define LDSM4(r, addr) \
    asm volatile("ldmatrix.sync.aligned.m8n8.x4.shared.b16 {%0,%1,%2,%3}, [%4];" \
        : "=r"((r)[0]), "=r"((r)[1]), "=r"((r)[2]), "=r"((r)[3]) : "r"(addr))

#define MMA16816(acc, a, b0, b1) \
    asm volatile("mma.sync.aligned.m16n8k16.row.col.f32.bf16.bf16.f32 " \
        "{%0,%1,%2,%3},{%4,%5,%6,%7},{%8,%9},{%0,%1,%2,%3};" \
        : "+f"((acc)[0]), "+f"((acc)[1]), "+f"((acc)[2]), "+f"((acc)[3]) \
        : "r"((a)[0]), "r"((a)[1]), "r"((a)[2]), "r"((a)[3]), "r"(b0), "r"(b1))

__device__ __forceinline__ uint32_t packbf(float lo, float hi) {
    __nv_bfloat162 v = __floats2bfloat162_rn(lo, hi);
    return *(uint32_t*)&v;
}
__device__ __forceinline__ void split1(float v, float& h, float& l) {
    __nv_bfloat16 hb = __float2bfloat16_rn(v);
    h = __bfloat162float(hb);
    l = v - h;                 // exact (Sterbenz), so h + l == v exactly
}
__device__ __forceinline__ float bf2f(uint32_t u, int hi) {
    __nv_bfloat162 p = *(__nv_bfloat162*)&u;
    return hi ? __bfloat162float(p.y) : __bfloat162float(p.x);
}

// ---------- prep: convert E once, zero accumulators ----------
__global__ void vq_prep(const float* __restrict__ E) {
    const int k = blockIdx.x * 128 + threadIdx.x;   // grid 4 x 128
    if (k == 0) { g_loss_acc = 0.0f; g_done = 0u; }
    float s = 0.f;
    #pragma unroll 8
    for (int d = 0; d < DDIM; d += 2) {
        float a0 = E[d * KC + k], a1 = E[(d + 1) * KC + k];
        s = fmaf(a0, a0, fmaf(a1, a1, s));
        float h0, l0, h1, l1;
        split1(a0, h0, l0); split1(a1, h1, l1);
        *(uint32_t*)(g_Ebuf + k * RS + d * 2)         = packbf(h0, h1);
        *(uint32_t*)(g_Ebuf + 73728 + k * RS + d * 2) = packbf(l0, l1);
    }
    g_hn[k] = 0.5f * s;
}

extern __shared__ unsigned char smem[];

__global__ __launch_bounds__(256, 1)
void vq_hmma_kernel(const float* __restrict__ x,
                    const float* __restrict__ E,
                    float* __restrict__ out, int loss_pos) {
    const int tid = threadIdx.x;
    const int w   = tid >> 5;
    const int l   = tid & 31;
    const int row0 = blockIdx.x * BM;
    const uint32_t sb = s2u(smem);
    float* hn   = (float*)(smem + HN_OFF);
    int*  idxs  = (int*)(smem + IDX_OFF);
    int*  fcnt  = (int*)(smem + CNT_OFF);
    int*  flagd = (int*)(smem + FL_OFF);
    __shared__ float warpsums[8];

    if (tid == 0) *fcnt = 0;

    // ---- async copy of converted E tables + hn into smem ----
    #pragma unroll
    for (int i = 0; i < 36; ++i) {
        uint32_t off = (uint32_t)(tid + i * 256) * 16;
        cpa16(sb + EH_OFF + off, g_Ebuf + off);
    }
    if (tid < 128) cpa16(sb + HN_OFF + tid * 16, (const unsigned char*)g_hn + tid * 16);
    CP_COMMIT();

    // ---- convert x tile into smem (overlaps with async copies) ----
    {
        const float4* x4 = (const float4*)x + (size_t)row0 * 16;
        #pragma unroll
        for (int i = 0; i < 8; ++i) {
            int idx = tid + i * 256;
            int r = idx >> 4, c4 = idx & 15;
            float4 v = x4[idx];
            float h0,l0,h1,l1,h2,l2,h3,l3;
            split1(v.x, h0, l0); split1(v.y, h1, l1);
            split1(v.z, h2, l2); split1(v.w, h3, l3);
            *(uint2*)(smem + XH_OFF + r * RS + c4 * 8) = make_uint2(packbf(h0, h1), packbf(h2, h3));
            *(uint2*)(smem + XL_OFF + r * RS + c4 * 8) = make_uint2(packbf(l0, l1), packbf(l2, l3));
        }
    }
    CP_WAIT0();
    __syncthreads();

    // ================= main: each warp does 16 rows x 512 codes =================
    uint32_t Ah[4][4], Al[4][4];
    {
        uint32_t abase = (uint32_t)((w * 16 + (l & 15)) * RS + ((l >> 4) << 4));
        #pragma unroll
        for (int ks = 0; ks < 4; ++ks) {
            LDSM4(Ah[ks], sb + XH_OFF + abase + ks * 32);
            LDSM4(Al[ks], sb + XL_OFF + abase + ks * 32);
        }
    }

    float b1_lo = -3.4e38f, b1_hi = -3.4e38f;
    float b2_lo = -3.4e38f, b2_hi = -3.4e38f;
    int   bi_lo = 0, bi_hi = 0;
    const uint32_t brow = (uint32_t)((l & 7) * RS + ((l >> 3) << 4));

    #pragma unroll 1
    for (int g = 0; g < 16; ++g) {
        float acc[4][4];
        #pragma unroll
        for (int t = 0; t < 4; ++t)
            #pragma unroll
            for (int j = 0; j < 4; ++j) acc[t][j] = 0.f;

        #pragma unroll
        for (int s = 0; s < 2; ++s) {
            uint32_t beh[4][4], bel[4][4];
            #pragma unroll
            for (int t = 0; t < 4; ++t) {
                uint32_t ro = (uint32_t)((g * 32 + t * 8) * RS + s * 64) + brow;
                LDSM4(beh[t], sb + EH_OFF + ro);
                LDSM4(bel[t], sb + EL_OFF + ro);
            }
            #pragma unroll
            for (int kk = 0; kk < 2; ++kk) {
                const int ks = 2 * s + kk;
                #pragma unroll
                for (int t = 0; t < 4; ++t)
                    MMA16816(acc[t], Ah[ks], beh[t][2 * kk], beh[t][2 * kk + 1]);
                #pragma unroll
                for (int t = 0; t < 4; ++t)
                    MMA16816(acc[t], Ah[ks], bel[t][2 * kk], bel[t][2 * kk + 1]);
                #pragma unroll
                for (int t = 0; t < 4; ++t)
                    MMA16816(acc[t], Al[ks], beh[t][2 * kk], beh[t][2 * kk + 1]);
            }
        }
        #pragma unroll
        for (int t = 0; t < 4; ++t) {
            const int col0 = g * 32 + t * 8 + 2 * (l & 3);
            float2 h2 = *(const float2*)(hn + col0);
            float sc;
            sc = acc[t][0] - h2.x;
            if (sc > b1_lo) { b2_lo = b1_lo; b1_lo = sc; bi_lo = col0; }
            else if (sc > b2_lo) b2_lo = sc;
            sc = acc[t][1] - h2.y;
            if (sc > b1_lo) { b2_lo = b1_lo; b1_lo = sc; bi_lo = col0 + 1; }
            else if (sc > b2_lo) b2_lo = sc;
            sc = acc[t][2] - h2.x;
            if (sc > b1_hi) { b2_hi = b1_hi; b1_hi = sc; bi_hi = col0; }
            else if (sc > b2_hi) b2_hi = sc;
            sc = acc[t][3] - h2.y;
            if (sc > b1_hi) { b2_hi = b1_hi; b1_hi = sc; bi_hi = col0 + 1; }
            else if (sc > b2_hi) b2_hi = sc;
        }
    }

    // reduce across the 4 lanes of each row-quad, carrying second-best
    #pragma unroll
    for (int m = 1; m < 4; m <<= 1) {
        float so, s2o; int io;
        so  = __shfl_xor_sync(0xffffffffu, b1_lo, m, 32);
        s2o = __shfl_xor_sync(0xffffffffu, b2_lo, m, 32);
        io  = __shfl_xor_sync(0xffffffffu, bi_lo, m, 32);
        b2_lo = fmaxf(fminf(b1_lo, so), fmaxf(b2_lo, s2o));
        if (so > b1_lo || (so == b1_lo && io < bi_lo)) { b1_lo = so; bi_lo = io; }
        so  = __shfl_xor_sync(0xffffffffu, b1_hi, m, 32);
        s2o = __shfl_xor_sync(0xffffffffu, b2_hi, m, 32);
        io  = __shfl_xor_sync(0xffffffffu, bi_hi, m, 32);
        b2_hi = fmaxf(fminf(b1_hi, so), fmaxf(b2_hi, s2o));
        if (so > b1_hi || (so == b1_hi && io < bi_hi)) { b1_hi = so; bi_hi = io; }
    }
    if ((l & 3) == 0) {
        const int r_lo = w * 16 + (l >> 2);
        const int r_hi = r_lo + 8;
        idxs[r_lo] = bi_lo;
        idxs[r_hi] = bi_hi;
        if (b1_lo - b2_lo < MARGIN_TAU) flagd[atomicAdd(fcnt, 1)] = r_lo;
        if (b1_hi - b2_hi < MARGIN_TAU) flagd[atomicAdd(fcnt, 1)] = r_hi;
    }
    __syncthreads();

    // ===== rescue: bit-exact replica of the R1 scalar scoring for flagged rows =====
    {
        const int cnt = *fcnt;
        for (int j = w; j < cnt; j += 8) {
            const int r = flagd[j];
            const float* xr = x + (size_t)(row0 + r) * DDIM;
            float s[16], t[16];
            #pragma unroll
            for (int i = 0; i < 16; ++i) { s[i] = 0.f; t[i] = 0.f; }
            #pragma unroll 4
            for (int d = 0; d < DDIM; ++d) {
                const float xd = xr[d];
                const float* Ed = E + d * KC + l;
                #pragma unroll
                for (int i = 0; i < 16; ++i) {
                    float e = Ed[i * 32];
                    s[i] = fmaf(xd, e, s[i]);
                    t[i] = fmaf(e, e, t[i]);
                }
            }
            float best = -3.4e38f; int bi = 0;
            #pragma unroll
            for (int i = 0; i < 16; ++i) {
                float sc = s[i] - 0.5f * t[i];
                int k = i * 32 + l;
                if (sc > best) { best = sc; bi = k; }
            }
            #pragma unroll
            for (int m = 1; m < 32; m <<= 1) {
                float so = __shfl_xor_sync(0xffffffffu, best, m, 32);
                int   io = __shfl_xor_sync(0xffffffffu, bi,   m, 32);
                if (so > best || (so == best && io < bi)) { best = so; bi = io; }
            }
            if (l == 0) idxs[r] = bi;
        }
    }
    __syncthreads();

    // ======= epilogue (all-smem, exact reconstruction): 2 threads per row =======
    float lp = 0.0f;
    {
        const int r = tid >> 1, half = tid & 1;
        const int k = idxs[r];
        const unsigned char* ehp = smem + EH_OFF + k * RS + half * 64;
        const unsigned char* elp = smem + EL_OFF + k * RS + half * 64;
        const unsigned char* xhp = smem + XH_OFF + r * RS + half * 64;
        const unsigned char* xlp = smem + XL_OFF + r * RS + half * 64;
        float4* og = (float4*)(out + (size_t)(row0 + r) * DDIM + half * 32);
        #pragma unroll
        for (int j = 0; j < 8; ++j) {
            uint32_t he = *(const uint32_t*)(ehp + j * 8);
            uint32_t he2 = *(const uint32_t*)(ehp + j * 8 + 4);
            uint32_t le = *(const uint32_t*)(elp + j * 8);
            uint32_t le2 = *(const uint32_t*)(elp + j * 8 + 4);
            uint32_t hx = *(const uint32_t*)(xhp + j * 8);
            uint32_t hx2 = *(const uint32_t*)(xhp + j * 8 + 4);
            uint32_t lx = *(const uint32_t*)(xlp + j * 8);
            uint32_t lx2 = *(const uint32_t*)(xlp + j * 8 + 4);
            float q0 = bf2f(he, 0) + bf2f(le, 0);
            float q1 = bf2f(he, 1) + bf2f(le, 1);
            float q2 = bf2f(he2, 0) + bf2f(le2, 0);
            float q3 = bf2f(he2, 1) + bf2f(le2, 1);
            float x0 = bf2f(hx, 0) + bf2f(lx, 0);
            float x1 = bf2f(hx, 1) + bf2f(lx, 1);
            float x2 = bf2f(hx2, 0) + bf2f(lx2, 0);
            float x3 = bf2f(hx2, 1) + bf2f(lx2, 1);
            float d0 = q0 - x0, d1 = q1 - x1, d2 = q2 - x2, d3 = q3 - x3;
            lp = fmaf(d0, d0, lp); lp = fmaf(d1, d1, lp);
            lp = fmaf(d2, d2, lp); lp = fmaf(d3, d3, lp);
            og[j] = make_float4(x0 + d0, x1 + d1, x2 + d2, x3 + d3);
        }
    }
    #pragma unroll
    for (int m = 16; m > 0; m >>= 1)
        lp += __shfl_xor_sync(0xffffffffu, lp, m, 32);
    if (l == 0) warpsums[w] = lp;
    __syncthreads();

    // single loss atomic per CTA; last CTA writes the final loss
    if (tid == 0) {
        float s = 0.f;
        #pragma unroll
        for (int i = 0; i < 8; ++i) s += warpsums[i];
        atomicAdd(&g_loss_acc, s);
        __threadfence();
        unsigned int o = atomicAdd(&g_done, 1u);
        if (o == (unsigned)(NBLK - 1)) {
            float tot = atomicAdd(&g_loss_acc, 0.0f);
            out[loss_pos] = 2.0f * tot / 8388608.0f;
        }
    }
}

extern "C" void kernel_launch(void* const* d_in, const int* in_sizes, int n_in,
                              void* d_out, int out_size) {
    const float* x = (const float*)d_in[0];   // [32,4096,64] fp32
    const float* E = (const float*)d_in[1];   // [64,512] fp32
    float* out = (float*)d_out;

    cudaFuncSetAttribute(vq_hmma_kernel,
                         cudaFuncAttributeMaxDynamicSharedMemorySize, SMEM_SZ);

    vq_prep<<<4, 128>>>(E);
    vq_hmma_kernel<<<NBLK, 256, SMEM_SZ>>>(x, E, out, out_size - 1);
}